// round 15
// baseline (speedup 1.0000x reference)
#include <cuda_runtime.h>
#include <cuda_fp16.h>
#include <cstdint>

#define NTOK 16384          // 8 * 2048 tokens per stream
#define DIM  256

// ---------------- scratch (device globals; no allocation allowed) ----------
__device__ uint32_t g_xq [NTOK * 128];   // LN out, fp16x2 d-pair packed
__device__ uint32_t g_xe [NTOK * 128];
__device__ uint32_t g_xl [NTOK * 128];
__device__ uint32_t g_wq [256 * 128];    // weights fp16x2 d-pair packed
__device__ uint32_t g_wk [256 * 128];
__device__ uint32_t g_wv [256 * 128];
__device__ uint32_t g_wo [256 * 128];
__device__ uint32_t g_qp [NTOK * 128];   // Q fp16x2 d-pair packed, pre-scaled
__device__ uint32_t g_k1p[NTOK * 128];
__device__ uint32_t g_k2p[NTOK * 128];
__device__ uint32_t g_v1p[(NTOK / 2) * DIM];   // V fp16x2 token-pair packed
__device__ uint32_t g_v2p[(NTOK / 2) * DIM];
__device__ uint32_t g_o0p[NTOK * 128];   // attention out fp16x2 d-pair packed
__device__ uint32_t g_o1p[NTOK * 128];

// ---------------- helpers ---------------------------------------------------
__device__ __forceinline__ uint32_t pack_f16(float hi, float lo) {
    uint32_t r;
    asm("cvt.rn.f16x2.f32 %0, %1, %2;" : "=r"(r) : "f"(hi), "f"(lo));
    return r;
}
__device__ __forceinline__ uint32_t ex2_h2(uint32_t x) {
    uint32_t r;
    asm("ex2.approx.f16x2 %0, %1;" : "=r"(r) : "r"(x));
    return r;
}
__device__ __forceinline__ uint32_t hadd2u(uint32_t a, uint32_t b) {
    __half2 x = *(__half2*)&a;
    __half2 y = *(__half2*)&b;
    __half2 z = __hadd2(x, y);
    return *(uint32_t*)&z;
}
__device__ __forceinline__ void mma16f(float* d, const uint32_t* a,
                                       uint32_t b0, uint32_t b1) {
    asm volatile(
        "mma.sync.aligned.m16n8k16.row.col.f32.f16.f16.f32 "
        "{%0,%1,%2,%3}, {%4,%5,%6,%7}, {%8,%9}, {%0,%1,%2,%3};"
        : "+f"(d[0]), "+f"(d[1]), "+f"(d[2]), "+f"(d[3])
        : "r"(a[0]), "r"(a[1]), "r"(a[2]), "r"(a[3]),
          "r"(b0), "r"(b1));
}
__device__ __forceinline__ void mma16h(uint32_t* d, const uint32_t* a,
                                       uint32_t b0, uint32_t b1) {
    asm volatile(
        "mma.sync.aligned.m16n8k16.row.col.f16.f16.f16.f16 "
        "{%0,%1}, {%2,%3,%4,%5}, {%6,%7}, {%0,%1};"
        : "+r"(d[0]), "+r"(d[1])
        : "r"(a[0]), "r"(a[1]), "r"(a[2]), "r"(a[3]),
          "r"(b0), "r"(b1));
}
__device__ __forceinline__ void ldsm4(uint32_t& r0, uint32_t& r1,
                                      uint32_t& r2, uint32_t& r3, uint32_t addr) {
    asm volatile(
        "ldmatrix.sync.aligned.m8n8.x4.shared.b16 {%0,%1,%2,%3}, [%4];"
        : "=r"(r0), "=r"(r1), "=r"(r2), "=r"(r3) : "r"(addr));
}
__device__ __forceinline__ uint32_t s2u(const void* p) {
    return (uint32_t)__cvta_generic_to_shared(p);
}
__device__ __forceinline__ void cp16(uint32_t dst, const void* src) {
    asm volatile("cp.async.cg.shared.global [%0], [%1], 16;" :: "r"(dst), "l"(src));
}
__device__ __forceinline__ void cp_commit() {
    asm volatile("cp.async.commit_group;");
}
__device__ __forceinline__ void cp_wait0() { asm volatile("cp.async.wait_group 0;"); }
__device__ __forceinline__ void cp_wait1() { asm volatile("cp.async.wait_group 1;"); }

// ---------------- fused LayerNorm + weight pack --------------------------------
__global__ void __launch_bounds__(256) lnw_kernel(
    const float* __restrict__ x,
    const float* __restrict__ gam, const float* __restrict__ bet,
    uint32_t* __restrict__ xq, uint32_t* __restrict__ xe, uint32_t* __restrict__ xl,
    const float* __restrict__ W0, const float* __restrict__ W1,
    const float* __restrict__ W2, const float* __restrict__ W3,
    uint32_t* __restrict__ P0, uint32_t* __restrict__ P1,
    uint32_t* __restrict__ P2, uint32_t* __restrict__ P3)
{
    if (blockIdx.x >= 6144) {
        int i = (blockIdx.x - 6144) * 256 + threadIdx.x;
        int w = i >> 15, idx = i & 32767;
        const float* W = w == 0 ? W0 : w == 1 ? W1 : w == 2 ? W2 : W3;
        uint32_t*    P = w == 0 ? P0 : w == 1 ? P1 : w == 2 ? P2 : P3;
        float2 v = *(const float2*)(W + 2 * idx);
        P[idx] = pack_f16(v.y, v.x);
        return;
    }

    int row  = blockIdx.x * 8 + (threadIdx.x >> 5);
    int lane = threadIdx.x & 31;

    const float4* src = (const float4*)(x + (size_t)row * DIM + lane * 8);
    float4 v0 = src[0], v1 = src[1];

    float s  = v0.x + v0.y + v0.z + v0.w + v1.x + v1.y + v1.z + v1.w;
    float ss = v0.x*v0.x + v0.y*v0.y + v0.z*v0.z + v0.w*v0.w
             + v1.x*v1.x + v1.y*v1.y + v1.z*v1.z + v1.w*v1.w;
#pragma unroll
    for (int o = 16; o; o >>= 1) {
        s  += __shfl_xor_sync(0xffffffffu, s,  o);
        ss += __shfl_xor_sync(0xffffffffu, ss, o);
    }
    float mu  = s * (1.0f / 256.0f);
    float var = ss * (1.0f / 256.0f) - mu * mu;
    float inv = rsqrtf(var + 1e-5f);

    int bidx = row / 6144;
    int n    = row - bidx * 6144;
    int strm = n >> 11;
    int i    = n & 2047;
    uint32_t* dst = (strm == 0 ? xq : (strm == 1 ? xe : xl))
                    + ((size_t)(bidx * 2048 + i)) * 128 + lane * 4;

    float4 g0 = *(const float4*)(gam + lane * 8);
    float4 g1 = *(const float4*)(gam + lane * 8 + 4);
    float4 b0 = *(const float4*)(bet + lane * 8);
    float4 b1 = *(const float4*)(bet + lane * 8 + 4);

    float o0x = (v0.x - mu) * inv * g0.x + b0.x;
    float o0y = (v0.y - mu) * inv * g0.y + b0.y;
    float o0z = (v0.z - mu) * inv * g0.z + b0.z;
    float o0w = (v0.w - mu) * inv * g0.w + b0.w;
    float o1x = (v1.x - mu) * inv * g1.x + b1.x;
    float o1y = (v1.y - mu) * inv * g1.y + b1.y;
    float o1z = (v1.z - mu) * inv * g1.z + b1.z;
    float o1w = (v1.w - mu) * inv * g1.w + b1.w;

    uint4 w = make_uint4(pack_f16(o0y, o0x), pack_f16(o0w, o0z),
                         pack_f16(o1y, o1x), pack_f16(o1w, o1z));
    *(uint4*)dst = w;
}

// ---------------- fp16 pipelined GEMM, 64-row M tiles --------------------------
// C[M,256] = (A [+ A2]) @ W^T + bias. Tile 64x128, grid (M/64, 2, jobs).
// 4 warps m (16 rows each) x 2 warps n (64 cols each).
// Modes: 0 f32 out (+bias*bscale); 1 V token-pair pack; 2 Q/K d-pair pack*ascale.
struct GemmJob {
    const uint32_t* A; const uint32_t* A2; const uint32_t* W; const float* B;
    float* C; uint32_t* Cp; float bscale; float ascale; int mode;
};
struct Jobs5 { GemmJob j[5]; };

template <int SUMA>
__global__ void __launch_bounds__(256, 2) gemm5h_kernel(Jobs5 jobs)
{
    extern __shared__ uint32_t hsm[];
    uint32_t* Abuf  = hsm;                                // [2][64][20]
    uint32_t* A2buf = hsm + 2 * 64 * 20;                  // (SUMA only)
    uint32_t* Wbuf  = hsm + (SUMA ? 4 : 2) * 64 * 20;     // [2][128][20]

    const GemmJob job = jobs.j[blockIdx.z];
    int tid  = threadIdx.x;
    int warp = tid >> 5, lane = tid & 31;
    int g = lane >> 2, tig = lane & 3;
    int wm = warp & 3, wn = warp >> 2;
    int m0 = blockIdx.x * 64, n0 = blockIdx.y * 128;

    float acc[8][4] = {};

    // cp.async coordinates: A 256 16B tasks (1/thread), W 512 (2/thread)
    int ra = tid >> 2,          ca = (tid & 3) * 4;        // A rows 0..63
    int rw0 = tid >> 2,         cw0 = (tid & 3) * 4;       // W rows 0..63
    int rw1 = (tid + 256) >> 2, cw1 = ((tid + 256) & 3) * 4; // W rows 64..127

    auto load = [&](int kc, int buf) {
        uint32_t* Ad = Abuf + buf * 64 * 20;
        uint32_t* Wd = Wbuf + buf * 128 * 20;
        cp16(s2u(&Ad[ra * 20 + ca]), job.A + (size_t)(m0 + ra) * 128 + kc * 16 + ca);
        if (SUMA) {
            uint32_t* A2d = A2buf + buf * 64 * 20;
            cp16(s2u(&A2d[ra * 20 + ca]), job.A2 + (size_t)(m0 + ra) * 128 + kc * 16 + ca);
        }
        cp16(s2u(&Wd[rw0 * 20 + cw0]), job.W + (size_t)(n0 + rw0) * 128 + kc * 16 + cw0);
        cp16(s2u(&Wd[rw1 * 20 + cw1]), job.W + (size_t)(n0 + rw1) * 128 + kc * 16 + cw1);
        cp_commit();
    };

    load(0, 0);

    uint32_t a_off = ((lane & 15) * 20 + (lane >> 4) * 4) * 4;
    uint32_t b_off = ((lane & 7) * 20 + (lane >> 3) * 4) * 4;

    for (int kc = 0; kc < 8; kc++) {
        int buf = kc & 1;
        cp_wait0();
        __syncthreads();
        if (kc < 7) load(kc + 1, 1 - buf);

        uint32_t a_base = s2u(Abuf + buf * 64 * 20);
        uint32_t w_base = s2u(Wbuf + buf * 128 * 20);

        uint32_t af[2][4];     // [sub k16][4]
#pragma unroll
        for (int sub = 0; sub < 2; sub++) {
            uint32_t addr = a_base + (wm * 16 * 20 + sub * 8) * 4 + a_off;
            ldsm4(af[sub][0], af[sub][1], af[sub][2], af[sub][3], addr);
            if (SUMA) {
                uint32_t a2_base = s2u(A2buf + buf * 64 * 20);
                uint32_t addr2 = a2_base + (wm * 16 * 20 + sub * 8) * 4 + a_off;
                uint32_t t0, t1, t2, t3;
                ldsm4(t0, t1, t2, t3, addr2);
                af[sub][0] = hadd2u(af[sub][0], t0);
                af[sub][1] = hadd2u(af[sub][1], t1);
                af[sub][2] = hadd2u(af[sub][2], t2);
                af[sub][3] = hadd2u(af[sub][3], t3);
            }
        }

        uint32_t bf[8][4];
#pragma unroll
        for (int ni = 0; ni < 8; ni++) {
            uint32_t addr = w_base + ((wn * 64 + ni * 8) * 20) * 4 + b_off;
            ldsm4(bf[ni][0], bf[ni][1], bf[ni][2], bf[ni][3], addr);
        }

#pragma unroll
        for (int sub = 0; sub < 2; sub++)
#pragma unroll
            for (int ni = 0; ni < 8; ni++)
                mma16f(acc[ni], af[sub], bf[ni][sub * 2], bf[ni][sub * 2 + 1]);
    }

    if (job.mode == 0) {
        int row = m0 + wm * 16 + g;
#pragma unroll
        for (int ni = 0; ni < 8; ni++) {
            int col = n0 + wn * 64 + ni * 8 + 2 * tig;
            float bb0 = job.B[col] * job.bscale;
            float bb1 = job.B[col + 1] * job.bscale;
            float2 r0v = make_float2(acc[ni][0] + bb0, acc[ni][1] + bb1);
            float2 r1v = make_float2(acc[ni][2] + bb0, acc[ni][3] + bb1);
            *(float2*)(job.C + (size_t)row * 256 + col)       = r0v;
            *(float2*)(job.C + (size_t)(row + 8) * 256 + col) = r1v;
        }
    } else if (job.mode == 1) {
        // token-pair packed fp16x2: word[pair][col] = (hi=row 2p+1, lo=row 2p)
        int base = m0 + wm * 16;
#pragma unroll
        for (int ni = 0; ni < 8; ni++) {
            int col = n0 + wn * 64 + ni * 8 + 2 * tig;
            float bb0 = job.B[col];
            float bb1 = job.B[col + 1];
            float v00 = acc[ni][0] + bb0;
            float v01 = acc[ni][1] + bb1;
            float v10 = acc[ni][2] + bb0;
            float v11 = acc[ni][3] + bb1;
            float p00 = __shfl_xor_sync(0xffffffffu, v00, 4);
            float p01 = __shfl_xor_sync(0xffffffffu, v01, 4);
            float p10 = __shfl_xor_sync(0xffffffffu, v10, 4);
            float p11 = __shfl_xor_sync(0xffffffffu, v11, 4);
            if ((g & 1) == 0) {
                int P0 = (base + g) >> 1;
                int P1 = (base + g + 8) >> 1;
                uint2 w0 = make_uint2(pack_f16(p00, v00), pack_f16(p01, v01));
                uint2 w1 = make_uint2(pack_f16(p10, v10), pack_f16(p11, v11));
                *(uint2*)(job.Cp + (size_t)P0 * 256 + col) = w0;
                *(uint2*)(job.Cp + (size_t)P1 * 256 + col) = w1;
            }
        }
    } else {
        // d-pair packed fp16x2: word[row][col/2] = (hi=col+1, lo=col), scaled
        float sc = job.ascale;
        int row = m0 + wm * 16 + g;
#pragma unroll
        for (int ni = 0; ni < 8; ni++) {
            int col = n0 + wn * 64 + ni * 8 + 2 * tig;
            float bb0 = job.B[col];
            float bb1 = job.B[col + 1];
            float v00 = (acc[ni][0] + bb0) * sc;
            float v01 = (acc[ni][1] + bb1) * sc;
            float v10 = (acc[ni][2] + bb0) * sc;
            float v11 = (acc[ni][3] + bb1) * sc;
            int wcol = col >> 1;
            job.Cp[(size_t)row * 128 + wcol]       = pack_f16(v01, v00);
            job.Cp[(size_t)(row + 8) * 128 + wcol] = pack_f16(v11, v10);
        }
    }
}

// ---------------- flash attention (R11 proven core, frozen) --------------------
// BM=256 (2 m-blocks/warp), BN=128, d=32. grid = 1024.
// 3-stage KV pipeline, 1 barrier/tile. fp16-acc QK, ldmatrix K, ones-MMA sums.
__global__ void __launch_bounds__(256, 2) attn_kernel(
    const uint32_t* __restrict__ Qp,
    const uint32_t* __restrict__ K1, const uint32_t* __restrict__ V1,
    const uint32_t* __restrict__ K2, const uint32_t* __restrict__ V2,
    uint32_t* __restrict__ O0, uint32_t* __restrict__ O1)
{
    extern __shared__ uint32_t smu[];
    uint32_t* KsB = smu;                 // [3][128][20] fp16x2 d-pair words
    uint32_t* VsB = smu + 3 * 128 * 20;  // [3][64][40]  fp16x2 token-pair words

    int bx = blockIdx.x;
    int qt = bx & 7, h = (bx >> 3) & 7, b = (bx >> 6) & 7, pass = bx >> 9;
    const uint32_t* Kp = pass ? K2 : K1;
    const uint32_t* Vp = pass ? V2 : V1;
    uint32_t* O = pass ? O1 : O0;

    int tid = threadIdx.x, warp = tid >> 5, lane = tid & 31;
    int g = lane >> 2, tig = lane & 3;

    const uint32_t ONES = 0x3C003C00u;   // fp16x2 (1.0, 1.0)

    // stage Q head slice (256 rows x 16 words) via cp.async
    {
        size_t qbase = (size_t)(b * 2048 + qt * 256) * 128 + h * 16;
#pragma unroll
        for (int it = 0; it < 4; it++) {
            int idx = tid + it * 256;
            int r = idx >> 2, c = (idx & 3) * 4;
            cp16(s2u(&KsB[r * 20 + c]), Qp + qbase + (size_t)r * 128 + c);
        }
        cp_commit();
        cp_wait0();
        __syncthreads();
    }

    uint32_t aqA[2][4], aqB[2][4];
#pragma unroll
    for (int kc = 0; kc < 2; kc++) {
        int rb = warp * 16 + g;
        aqA[kc][0] = KsB[rb * 20 + kc * 8 + tig];
        aqA[kc][1] = KsB[(rb + 8) * 20 + kc * 8 + tig];
        aqA[kc][2] = KsB[rb * 20 + kc * 8 + tig + 4];
        aqA[kc][3] = KsB[(rb + 8) * 20 + kc * 8 + tig + 4];
        int rc = rb + 128;
        aqB[kc][0] = KsB[rc * 20 + kc * 8 + tig];
        aqB[kc][1] = KsB[(rc + 8) * 20 + kc * 8 + tig];
        aqB[kc][2] = KsB[rc * 20 + kc * 8 + tig + 4];
        aqB[kc][3] = KsB[(rc + 8) * 20 + kc * 8 + tig + 4];
    }
    __syncthreads();

    int kra = tid >> 2,         kca = (tid & 3) * 4;
    int krb = (tid + 256) >> 2, kcb = ((tid + 256) & 3) * 4;
    int vra = tid >> 3,         vca = (tid & 7) * 4;
    int vrb = (tid + 256) >> 3, vcb = ((tid + 256) & 7) * 4;

    auto issue = [&](int j, int s) {
        size_t kbase = (size_t)(b * 2048 + j * 128) * 128 + h * 16;
        size_t vbase = (size_t)(b * 1024 + j * 64) * 256 + h * 32;
        uint32_t* Kd = KsB + s * 128 * 20;
        uint32_t* Vd = VsB + s * 64 * 40;
        cp16(s2u(&Kd[kra * 20 + kca]), Kp + kbase + (size_t)kra * 128 + kca);
        cp16(s2u(&Kd[krb * 20 + kcb]), Kp + kbase + (size_t)krb * 128 + kcb);
        cp16(s2u(&Vd[vra * 40 + vca]), Vp + vbase + (size_t)vra * 256 + vca);
        cp16(s2u(&Vd[vrb * 40 + vcb]), Vp + vbase + (size_t)vrb * 256 + vcb);
        cp_commit();
    };

    issue(0, 0);
    issue(1, 1);

    uint32_t kls_off = ((lane & 7) * 20 + (lane >> 3) * 4) * 4;
    uint32_t ks_base = s2u(KsB);

    float oaccA[4][4] = {}, oaccB[4][4] = {};
    float sumA[4] = {}, sumB[4] = {};

    int stage = 0, wstage = 2;

#pragma unroll 1
    for (int j = 0; j < 16; j++) {
        if (j < 15) cp_wait1(); else cp_wait0();
        __syncthreads();
        if (j + 2 <= 15) issue(j + 2, wstage);

        uint32_t kaddr = ks_base + stage * (128 * 20 * 4) + kls_off;
        const uint32_t* Vb = VsB + stage * 64 * 40;

#pragma unroll
        for (int p = 0; p < 8; p++) {
            uint32_t k0r[4], k1r[4];
            ldsm4(k0r[0], k0r[1], k0r[2], k0r[3], kaddr + p * 1280);
            ldsm4(k1r[0], k1r[1], k1r[2], k1r[3], kaddr + p * 1280 + 640);

            uint32_t sA0[2] = {0u, 0u}, sA1[2] = {0u, 0u};
            uint32_t sB0[2] = {0u, 0u}, sB1[2] = {0u, 0u};
            mma16h(sA0, aqA[0], k0r[0], k0r[1]);
            mma16h(sA0, aqA[1], k0r[2], k0r[3]);
            mma16h(sB0, aqB[0], k0r[0], k0r[1]);
            mma16h(sB0, aqB[1], k0r[2], k0r[3]);
            mma16h(sA1, aqA[0], k1r[0], k1r[1]);
            mma16h(sA1, aqA[1], k1r[2], k1r[3]);
            mma16h(sB1, aqB[0], k1r[0], k1r[1]);
            mma16h(sB1, aqB[1], k1r[2], k1r[3]);

            uint32_t apA[4], apB[4];
            apA[0] = ex2_h2(sA0[0]);
            apA[1] = ex2_h2(sA0[1]);
            apA[2] = ex2_h2(sA1[0]);
            apA[3] = ex2_h2(sA1[1]);
            apB[0] = ex2_h2(sB0[0]);
            apB[1] = ex2_h2(sB0[1]);
            apB[2] = ex2_h2(sB1[0]);
            apB[3] = ex2_h2(sB1[1]);

            const uint32_t* v0 = Vb + (p * 8 + tig) * 40;
            const uint32_t* v1 = Vb + (p * 8 + tig + 4) * 40;
#pragma unroll
            for (int m = 0; m < 4; m++) {
                uint32_t vb0 = v0[m * 8 + g];
                uint32_t vb1 = v1[m * 8 + g];
                mma16f(oaccA[m], apA, vb0, vb1);
                mma16f(oaccB[m], apB, vb0, vb1);
            }
            mma16f(sumA, apA, ONES, ONES);
            mma16f(sumB, apB, ONES, ONES);
        }

        stage  = stage  == 2 ? 0 : stage + 1;
        wstage = wstage == 2 ? 0 : wstage + 1;
    }

    float iA0 = 1.0f / sumA[0], iA1 = 1.0f / sumA[2];
    float iB0 = 1.0f / sumB[0], iB1 = 1.0f / sumB[2];

    int rowA = b * 2048 + qt * 256 + warp * 16 + g;
    int rowB = rowA + 128;
#pragma unroll
    for (int m = 0; m < 4; m++) {
        int wcol = h * 16 + m * 4 + tig;
        O[(size_t)rowA * 128 + wcol] =
            pack_f16(oaccA[m][1] * iA0, oaccA[m][0] * iA0);
        O[(size_t)(rowA + 8) * 128 + wcol] =
            pack_f16(oaccA[m][3] * iA1, oaccA[m][2] * iA1);
        O[(size_t)rowB * 128 + wcol] =
            pack_f16(oaccB[m][1] * iB0, oaccB[m][0] * iB0);
        O[(size_t)(rowB + 8) * 128 + wcol] =
            pack_f16(oaccB[m][3] * iB1, oaccB[m][2] * iB1);
    }
}

// ---------------- launcher ------------------------------------------------------
extern "C" void kernel_launch(void* const* d_in, const int* in_sizes, int n_in,
                              void* d_out, int out_size)
{
    (void)in_sizes; (void)n_in; (void)out_size;
    const float* x    = (const float*)d_in[0];
    const float* ln_g = (const float*)d_in[1];
    const float* ln_b = (const float*)d_in[2];
    const float* Wq   = (const float*)d_in[3];
    const float* bq   = (const float*)d_in[4];
    const float* Wk   = (const float*)d_in[5];
    const float* bk   = (const float*)d_in[6];
    const float* Wv   = (const float*)d_in[7];
    const float* bv   = (const float*)d_in[8];
    const float* Wo   = (const float*)d_in[9];
    const float* bo   = (const float*)d_in[10];
    float* out = (float*)d_out;

    uint32_t *xq, *xe, *xl, *wq, *wk, *wv, *wo;
    uint32_t *qp, *k1p, *k2p, *v1p, *v2p, *o0p, *o1p;
    cudaGetSymbolAddress((void**)&xq,  g_xq);
    cudaGetSymbolAddress((void**)&xe,  g_xe);
    cudaGetSymbolAddress((void**)&xl,  g_xl);
    cudaGetSymbolAddress((void**)&wq,  g_wq);
    cudaGetSymbolAddress((void**)&wk,  g_wk);
    cudaGetSymbolAddress((void**)&wv,  g_wv);
    cudaGetSymbolAddress((void**)&wo,  g_wo);
    cudaGetSymbolAddress((void**)&qp,  g_qp);
    cudaGetSymbolAddress((void**)&k1p, g_k1p);
    cudaGetSymbolAddress((void**)&k2p, g_k2p);
    cudaGetSymbolAddress((void**)&v1p, g_v1p);
    cudaGetSymbolAddress((void**)&v2p, g_v2p);
    cudaGetSymbolAddress((void**)&o0p, g_o0p);
    cudaGetSymbolAddress((void**)&o1p, g_o1p);

    const int GSMEM0 = (2 * 64 * 20 + 2 * 128 * 20) * 4;   // 30720 B
    const int GSMEM1 = (4 * 64 * 20 + 2 * 128 * 20) * 4;   // 40960 B
    const int ASMEM  = (3 * 128 * 20 + 3 * 64 * 40) * 4;   // 61440 B
    cudaFuncSetAttribute(attn_kernel,      cudaFuncAttributeMaxDynamicSharedMemorySize, ASMEM);
    cudaFuncSetAttribute(gemm5h_kernel<0>, cudaFuncAttributeMaxDynamicSharedMemorySize, GSMEM0);
    cudaFuncSetAttribute(gemm5h_kernel<1>, cudaFuncAttributeMaxDynamicSharedMemorySize, GSMEM1);

    lnw_kernel<<<6656, 256>>>(x, ln_g, ln_b, xq, xe, xl,
                              Wq, Wk, Wv, Wo, wq, wk, wv, wo);            // launch 1

    const float QSC = 0.0625f * 1.44269504f;   // dim^-0.5 * log2(e)
    Jobs5 jobs = {{
        { xq, nullptr, wq, bq, nullptr, qp,  1.0f, QSC,  2 },
        { xe, nullptr, wk, bk, nullptr, k1p, 1.0f, 1.0f, 2 },
        { xe, nullptr, wv, bv, nullptr, v1p, 1.0f, 1.0f, 1 },
        { xl, nullptr, wk, bk, nullptr, k2p, 1.0f, 1.0f, 2 },
        { xl, nullptr, wv, bv, nullptr, v2p, 1.0f, 1.0f, 1 },
    }};
    gemm5h_kernel<0><<<dim3(256, 2, 5), 256, GSMEM0>>>(jobs);             // launch 2

    attn_kernel<<<1024, 256, ASMEM>>>(qp, k1p, v1p, k2p, v2p, o0p, o1p);  // launch 3

    // out = (o0 + o1) @ Wo^T + 2*bo
    Jobs5 ojob = {{
        { o0p, o1p, wo, bo, out, nullptr, 2.0f, 1.0f, 0 },
        { o0p, o1p, wo, bo, out, nullptr, 2.0f, 1.0f, 0 },
        { o0p, o1p, wo, bo, out, nullptr, 2.0f, 1.0f, 0 },
        { o0p, o1p, wo, bo, out, nullptr, 2.0f, 1.0f, 0 },
        { o0p, o1p, wo, bo, out, nullptr, 2.0f, 1.0f, 0 },
    }};
    gemm5h_kernel<1><<<dim3(256, 2, 1), 256, GSMEM1>>>(ojob);             // launch 4
}

// round 16
// speedup vs baseline: 1.0746x; 1.0746x over previous
#include <cuda_runtime.h>
#include <cuda_fp16.h>
#include <cstdint>

#define NTOK 16384          // 8 * 2048 tokens per stream
#define DIM  256

// ---------------- scratch (device globals; no allocation allowed) ----------
__device__ uint32_t g_xq [NTOK * 128];   // LN out, fp16x2 d-pair packed
__device__ uint32_t g_xe [NTOK * 128];
__device__ uint32_t g_xl [NTOK * 128];
__device__ uint32_t g_wq [256 * 128];    // weights fp16x2 d-pair packed
__device__ uint32_t g_wk [256 * 128];
__device__ uint32_t g_wv [256 * 128];
__device__ uint32_t g_wo [256 * 128];
__device__ uint32_t g_qp [NTOK * 128];   // Q fp16x2 d-pair packed, pre-scaled
__device__ uint32_t g_k1p[NTOK * 128];
__device__ uint32_t g_k2p[NTOK * 128];
__device__ uint32_t g_v1p[(NTOK / 2) * DIM];   // V fp16x2 token-pair packed
__device__ uint32_t g_v2p[(NTOK / 2) * DIM];
__device__ uint32_t g_o0p[NTOK * 128];   // attention out fp16x2 d-pair packed
__device__ uint32_t g_o1p[NTOK * 128];

// ---------------- helpers ---------------------------------------------------
__device__ __forceinline__ uint32_t pack_f16(float hi, float lo) {
    uint32_t r;
    asm("cvt.rn.f16x2.f32 %0, %1, %2;" : "=r"(r) : "f"(hi), "f"(lo));
    return r;
}
__device__ __forceinline__ uint32_t ex2_h2(uint32_t x) {
    uint32_t r;
    asm("ex2.approx.f16x2 %0, %1;" : "=r"(r) : "r"(x));
    return r;
}
__device__ __forceinline__ uint32_t hadd2u(uint32_t a, uint32_t b) {
    __half2 x = *(__half2*)&a;
    __half2 y = *(__half2*)&b;
    __half2 z = __hadd2(x, y);
    return *(uint32_t*)&z;
}
__device__ __forceinline__ void mma16f(float* d, const uint32_t* a,
                                       uint32_t b0, uint32_t b1) {
    asm volatile(
        "mma.sync.aligned.m16n8k16.row.col.f32.f16.f16.f32 "
        "{%0,%1,%2,%3}, {%4,%5,%6,%7}, {%8,%9}, {%0,%1,%2,%3};"
        : "+f"(d[0]), "+f"(d[1]), "+f"(d[2]), "+f"(d[3])
        : "r"(a[0]), "r"(a[1]), "r"(a[2]), "r"(a[3]),
          "r"(b0), "r"(b1));
}
__device__ __forceinline__ void mma16h(uint32_t* d, const uint32_t* a,
                                       uint32_t b0, uint32_t b1) {
    asm volatile(
        "mma.sync.aligned.m16n8k16.row.col.f16.f16.f16.f16 "
        "{%0,%1}, {%2,%3,%4,%5}, {%6,%7}, {%0,%1};"
        : "+r"(d[0]), "+r"(d[1])
        : "r"(a[0]), "r"(a[1]), "r"(a[2]), "r"(a[3]),
          "r"(b0), "r"(b1));
}
__device__ __forceinline__ void ldsm4(uint32_t& r0, uint32_t& r1,
                                      uint32_t& r2, uint32_t& r3, uint32_t addr) {
    asm volatile(
        "ldmatrix.sync.aligned.m8n8.x4.shared.b16 {%0,%1,%2,%3}, [%4];"
        : "=r"(r0), "=r"(r1), "=r"(r2), "=r"(r3) : "r"(addr));
}
__device__ __forceinline__ uint32_t s2u(const void* p) {
    return (uint32_t)__cvta_generic_to_shared(p);
}
__device__ __forceinline__ void cp16(uint32_t dst, const void* src) {
    asm volatile("cp.async.cg.shared.global [%0], [%1], 16;" :: "r"(dst), "l"(src));
}
__device__ __forceinline__ void cp_commit() {
    asm volatile("cp.async.commit_group;");
}
__device__ __forceinline__ void cp_wait0() { asm volatile("cp.async.wait_group 0;"); }
__device__ __forceinline__ void cp_wait1() { asm volatile("cp.async.wait_group 1;"); }

// ---------------- fused LayerNorm + weight pack --------------------------------
__global__ void __launch_bounds__(256) lnw_kernel(
    const float* __restrict__ x,
    const float* __restrict__ gam, const float* __restrict__ bet,
    uint32_t* __restrict__ xq, uint32_t* __restrict__ xe, uint32_t* __restrict__ xl,
    const float* __restrict__ W0, const float* __restrict__ W1,
    const float* __restrict__ W2, const float* __restrict__ W3,
    uint32_t* __restrict__ P0, uint32_t* __restrict__ P1,
    uint32_t* __restrict__ P2, uint32_t* __restrict__ P3)
{
    if (blockIdx.x >= 6144) {
        int i = (blockIdx.x - 6144) * 256 + threadIdx.x;
        int w = i >> 15, idx = i & 32767;
        const float* W = w == 0 ? W0 : w == 1 ? W1 : w == 2 ? W2 : W3;
        uint32_t*    P = w == 0 ? P0 : w == 1 ? P1 : w == 2 ? P2 : P3;
        float2 v = *(const float2*)(W + 2 * idx);
        P[idx] = pack_f16(v.y, v.x);
        return;
    }

    int row  = blockIdx.x * 8 + (threadIdx.x >> 5);
    int lane = threadIdx.x & 31;

    const float4* src = (const float4*)(x + (size_t)row * DIM + lane * 8);
    float4 v0 = src[0], v1 = src[1];

    float s  = v0.x + v0.y + v0.z + v0.w + v1.x + v1.y + v1.z + v1.w;
    float ss = v0.x*v0.x + v0.y*v0.y + v0.z*v0.z + v0.w*v0.w
             + v1.x*v1.x + v1.y*v1.y + v1.z*v1.z + v1.w*v1.w;
#pragma unroll
    for (int o = 16; o; o >>= 1) {
        s  += __shfl_xor_sync(0xffffffffu, s,  o);
        ss += __shfl_xor_sync(0xffffffffu, ss, o);
    }
    float mu  = s * (1.0f / 256.0f);
    float var = ss * (1.0f / 256.0f) - mu * mu;
    float inv = rsqrtf(var + 1e-5f);

    int bidx = row / 6144;
    int n    = row - bidx * 6144;
    int strm = n >> 11;
    int i    = n & 2047;
    uint32_t* dst = (strm == 0 ? xq : (strm == 1 ? xe : xl))
                    + ((size_t)(bidx * 2048 + i)) * 128 + lane * 4;

    float4 g0 = *(const float4*)(gam + lane * 8);
    float4 g1 = *(const float4*)(gam + lane * 8 + 4);
    float4 b0 = *(const float4*)(bet + lane * 8);
    float4 b1 = *(const float4*)(bet + lane * 8 + 4);

    float o0x = (v0.x - mu) * inv * g0.x + b0.x;
    float o0y = (v0.y - mu) * inv * g0.y + b0.y;
    float o0z = (v0.z - mu) * inv * g0.z + b0.z;
    float o0w = (v0.w - mu) * inv * g0.w + b0.w;
    float o1x = (v1.x - mu) * inv * g1.x + b1.x;
    float o1y = (v1.y - mu) * inv * g1.y + b1.y;
    float o1z = (v1.z - mu) * inv * g1.z + b1.z;
    float o1w = (v1.w - mu) * inv * g1.w + b1.w;

    uint4 w = make_uint4(pack_f16(o0y, o0x), pack_f16(o0w, o0z),
                         pack_f16(o1y, o1x), pack_f16(o1w, o1z));
    *(uint4*)dst = w;
}

// ---------------- fp16 GEMM, 128-row M tiles, 3-stage pipeline -----------------
// C[M,256] = (A [+ A2]) @ W^T + bias. Tile 128x128, grid (128, 2, jobs).
// 3 smem stages, 2 loads in flight, wait_group 1 (attention-proven pattern).
struct GemmJob {
    const uint32_t* A; const uint32_t* A2; const uint32_t* W; const float* B;
    float* C; uint32_t* Cp; float bscale; float ascale; int mode;
};
struct Jobs5 { GemmJob j[5]; };

template <int SUMA>
__global__ void __launch_bounds__(256, 2) gemm5h_kernel(Jobs5 jobs)
{
    extern __shared__ uint32_t hsm[];
    uint32_t* Abuf  = hsm;                               // [3][128][20]
    uint32_t* A2buf = hsm + 3 * 128 * 20;                // (SUMA only)
    uint32_t* Wbuf  = hsm + (SUMA ? 6 : 3) * 128 * 20;   // [3][128][20]

    const GemmJob job = jobs.j[blockIdx.z];
    int tid  = threadIdx.x;
    int warp = tid >> 5, lane = tid & 31;
    int g = lane >> 2, tig = lane & 3;
    int wm = warp & 3, wn = warp >> 2;
    int m0 = blockIdx.x * 128, n0 = blockIdx.y * 128;

    float acc[2][8][4] = {};

    int r0 = tid >> 2,         c0 = (tid & 3) * 4;
    int r1 = (tid + 256) >> 2, c1 = ((tid + 256) & 3) * 4;

    auto load = [&](int kc, int buf) {
        uint32_t* Ad = Abuf + buf * 128 * 20;
        uint32_t* Wd = Wbuf + buf * 128 * 20;
        cp16(s2u(&Ad[r0 * 20 + c0]), job.A + (size_t)(m0 + r0) * 128 + kc * 16 + c0);
        cp16(s2u(&Ad[r1 * 20 + c1]), job.A + (size_t)(m0 + r1) * 128 + kc * 16 + c1);
        if (SUMA) {
            uint32_t* A2d = A2buf + buf * 128 * 20;
            cp16(s2u(&A2d[r0 * 20 + c0]), job.A2 + (size_t)(m0 + r0) * 128 + kc * 16 + c0);
            cp16(s2u(&A2d[r1 * 20 + c1]), job.A2 + (size_t)(m0 + r1) * 128 + kc * 16 + c1);
        }
        cp16(s2u(&Wd[r0 * 20 + c0]), job.W + (size_t)(n0 + r0) * 128 + kc * 16 + c0);
        cp16(s2u(&Wd[r1 * 20 + c1]), job.W + (size_t)(n0 + r1) * 128 + kc * 16 + c1);
        cp_commit();
    };

    load(0, 0);
    load(1, 1);

    uint32_t a_off = ((lane & 15) * 20 + (lane >> 4) * 4) * 4;
    uint32_t b_off = ((lane & 7) * 20 + (lane >> 3) * 4) * 4;

    int stage = 0, wstage = 2;

    for (int kc = 0; kc < 8; kc++) {
        if (kc < 7) cp_wait1(); else cp_wait0();
        __syncthreads();
        if (kc + 2 <= 7) load(kc + 2, wstage);

        uint32_t a_base = s2u(Abuf + stage * 128 * 20);
        uint32_t w_base = s2u(Wbuf + stage * 128 * 20);

        uint32_t af[2][2][4];
#pragma unroll
        for (int mi = 0; mi < 2; mi++)
#pragma unroll
            for (int sub = 0; sub < 2; sub++) {
                uint32_t addr = a_base + ((wm * 32 + mi * 16) * 20 + sub * 8) * 4 + a_off;
                ldsm4(af[mi][sub][0], af[mi][sub][1], af[mi][sub][2], af[mi][sub][3], addr);
                if (SUMA) {
                    uint32_t a2_base = s2u(A2buf + stage * 128 * 20);
                    uint32_t addr2 = a2_base + ((wm * 32 + mi * 16) * 20 + sub * 8) * 4 + a_off;
                    uint32_t t0, t1, t2, t3;
                    ldsm4(t0, t1, t2, t3, addr2);
                    af[mi][sub][0] = hadd2u(af[mi][sub][0], t0);
                    af[mi][sub][1] = hadd2u(af[mi][sub][1], t1);
                    af[mi][sub][2] = hadd2u(af[mi][sub][2], t2);
                    af[mi][sub][3] = hadd2u(af[mi][sub][3], t3);
                }
            }

        uint32_t bf[8][4];
#pragma unroll
        for (int ni = 0; ni < 8; ni++) {
            uint32_t addr = w_base + ((wn * 64 + ni * 8) * 20) * 4 + b_off;
            ldsm4(bf[ni][0], bf[ni][1], bf[ni][2], bf[ni][3], addr);
        }

#pragma unroll
        for (int sub = 0; sub < 2; sub++)
#pragma unroll
            for (int mi = 0; mi < 2; mi++)
#pragma unroll
                for (int ni = 0; ni < 8; ni++)
                    mma16f(acc[mi][ni], af[mi][sub], bf[ni][sub * 2], bf[ni][sub * 2 + 1]);

        stage  = stage  == 2 ? 0 : stage + 1;
        wstage = wstage == 2 ? 0 : wstage + 1;
    }

    if (job.mode == 0) {
#pragma unroll
        for (int mi = 0; mi < 2; mi++) {
            int row = m0 + wm * 32 + mi * 16 + g;
#pragma unroll
            for (int ni = 0; ni < 8; ni++) {
                int col = n0 + wn * 64 + ni * 8 + 2 * tig;
                float bb0 = job.B[col] * job.bscale;
                float bb1 = job.B[col + 1] * job.bscale;
                float2 r0v = make_float2(acc[mi][ni][0] + bb0, acc[mi][ni][1] + bb1);
                float2 r1v = make_float2(acc[mi][ni][2] + bb0, acc[mi][ni][3] + bb1);
                *(float2*)(job.C + (size_t)row * 256 + col)       = r0v;
                *(float2*)(job.C + (size_t)(row + 8) * 256 + col) = r1v;
            }
        }
    } else if (job.mode == 1) {
#pragma unroll
        for (int mi = 0; mi < 2; mi++) {
            int base = m0 + wm * 32 + mi * 16;
#pragma unroll
            for (int ni = 0; ni < 8; ni++) {
                int col = n0 + wn * 64 + ni * 8 + 2 * tig;
                float bb0 = job.B[col];
                float bb1 = job.B[col + 1];
                float v00 = acc[mi][ni][0] + bb0;
                float v01 = acc[mi][ni][1] + bb1;
                float v10 = acc[mi][ni][2] + bb0;
                float v11 = acc[mi][ni][3] + bb1;
                float p00 = __shfl_xor_sync(0xffffffffu, v00, 4);
                float p01 = __shfl_xor_sync(0xffffffffu, v01, 4);
                float p10 = __shfl_xor_sync(0xffffffffu, v10, 4);
                float p11 = __shfl_xor_sync(0xffffffffu, v11, 4);
                if ((g & 1) == 0) {
                    int P0 = (base + g) >> 1;
                    int P1 = (base + g + 8) >> 1;
                    uint2 w0 = make_uint2(pack_f16(p00, v00), pack_f16(p01, v01));
                    uint2 w1 = make_uint2(pack_f16(p10, v10), pack_f16(p11, v11));
                    *(uint2*)(job.Cp + (size_t)P0 * 256 + col) = w0;
                    *(uint2*)(job.Cp + (size_t)P1 * 256 + col) = w1;
                }
            }
        }
    } else {
        float sc = job.ascale;
#pragma unroll
        for (int mi = 0; mi < 2; mi++) {
            int row = m0 + wm * 32 + mi * 16 + g;
#pragma unroll
            for (int ni = 0; ni < 8; ni++) {
                int col = n0 + wn * 64 + ni * 8 + 2 * tig;
                float bb0 = job.B[col];
                float bb1 = job.B[col + 1];
                float v00 = (acc[mi][ni][0] + bb0) * sc;
                float v01 = (acc[mi][ni][1] + bb1) * sc;
                float v10 = (acc[mi][ni][2] + bb0) * sc;
                float v11 = (acc[mi][ni][3] + bb1) * sc;
                int wcol = col >> 1;
                job.Cp[(size_t)row * 128 + wcol]       = pack_f16(v01, v00);
                job.Cp[(size_t)(row + 8) * 128 + wcol] = pack_f16(v11, v10);
            }
        }
    }
}

// ---------------- flash attention (R11 proven core, frozen) --------------------
// BM=256 (2 m-blocks/warp), BN=128, d=32. grid = 1024.
// 3-stage KV pipeline, 1 barrier/tile. fp16-acc QK, ldmatrix K, ones-MMA sums.
__global__ void __launch_bounds__(256, 2) attn_kernel(
    const uint32_t* __restrict__ Qp,
    const uint32_t* __restrict__ K1, const uint32_t* __restrict__ V1,
    const uint32_t* __restrict__ K2, const uint32_t* __restrict__ V2,
    uint32_t* __restrict__ O0, uint32_t* __restrict__ O1)
{
    extern __shared__ uint32_t smu[];
    uint32_t* KsB = smu;                 // [3][128][20] fp16x2 d-pair words
    uint32_t* VsB = smu + 3 * 128 * 20;  // [3][64][40]  fp16x2 token-pair words

    int bx = blockIdx.x;
    int qt = bx & 7, h = (bx >> 3) & 7, b = (bx >> 6) & 7, pass = bx >> 9;
    const uint32_t* Kp = pass ? K2 : K1;
    const uint32_t* Vp = pass ? V2 : V1;
    uint32_t* O = pass ? O1 : O0;

    int tid = threadIdx.x, warp = tid >> 5, lane = tid & 31;
    int g = lane >> 2, tig = lane & 3;

    const uint32_t ONES = 0x3C003C00u;   // fp16x2 (1.0, 1.0)

    // stage Q head slice (256 rows x 16 words) via cp.async
    {
        size_t qbase = (size_t)(b * 2048 + qt * 256) * 128 + h * 16;
#pragma unroll
        for (int it = 0; it < 4; it++) {
            int idx = tid + it * 256;
            int r = idx >> 2, c = (idx & 3) * 4;
            cp16(s2u(&KsB[r * 20 + c]), Qp + qbase + (size_t)r * 128 + c);
        }
        cp_commit();
        cp_wait0();
        __syncthreads();
    }

    uint32_t aqA[2][4], aqB[2][4];
#pragma unroll
    for (int kc = 0; kc < 2; kc++) {
        int rb = warp * 16 + g;
        aqA[kc][0] = KsB[rb * 20 + kc * 8 + tig];
        aqA[kc][1] = KsB[(rb + 8) * 20 + kc * 8 + tig];
        aqA[kc][2] = KsB[rb * 20 + kc * 8 + tig + 4];
        aqA[kc][3] = KsB[(rb + 8) * 20 + kc * 8 + tig + 4];
        int rc = rb + 128;
        aqB[kc][0] = KsB[rc * 20 + kc * 8 + tig];
        aqB[kc][1] = KsB[(rc + 8) * 20 + kc * 8 + tig];
        aqB[kc][2] = KsB[rc * 20 + kc * 8 + tig + 4];
        aqB[kc][3] = KsB[(rc + 8) * 20 + kc * 8 + tig + 4];
    }
    __syncthreads();

    int kra = tid >> 2,         kca = (tid & 3) * 4;
    int krb = (tid + 256) >> 2, kcb = ((tid + 256) & 3) * 4;
    int vra = tid >> 3,         vca = (tid & 7) * 4;
    int vrb = (tid + 256) >> 3, vcb = ((tid + 256) & 7) * 4;

    auto issue = [&](int j, int s) {
        size_t kbase = (size_t)(b * 2048 + j * 128) * 128 + h * 16;
        size_t vbase = (size_t)(b * 1024 + j * 64) * 256 + h * 32;
        uint32_t* Kd = KsB + s * 128 * 20;
        uint32_t* Vd = VsB + s * 64 * 40;
        cp16(s2u(&Kd[kra * 20 + kca]), Kp + kbase + (size_t)kra * 128 + kca);
        cp16(s2u(&Kd[krb * 20 + kcb]), Kp + kbase + (size_t)krb * 128 + kcb);
        cp16(s2u(&Vd[vra * 40 + vca]), Vp + vbase + (size_t)vra * 256 + vca);
        cp16(s2u(&Vd[vrb * 40 + vcb]), Vp + vbase + (size_t)vrb * 256 + vcb);
        cp_commit();
    };

    issue(0, 0);
    issue(1, 1);

    uint32_t kls_off = ((lane & 7) * 20 + (lane >> 3) * 4) * 4;
    uint32_t ks_base = s2u(KsB);

    float oaccA[4][4] = {}, oaccB[4][4] = {};
    float sumA[4] = {}, sumB[4] = {};

    int stage = 0, wstage = 2;

#pragma unroll 1
    for (int j = 0; j < 16; j++) {
        if (j < 15) cp_wait1(); else cp_wait0();
        __syncthreads();
        if (j + 2 <= 15) issue(j + 2, wstage);

        uint32_t kaddr = ks_base + stage * (128 * 20 * 4) + kls_off;
        const uint32_t* Vb = VsB + stage * 64 * 40;

#pragma unroll
        for (int p = 0; p < 8; p++) {
            uint32_t k0r[4], k1r[4];
            ldsm4(k0r[0], k0r[1], k0r[2], k0r[3], kaddr + p * 1280);
            ldsm4(k1r[0], k1r[1], k1r[2], k1r[3], kaddr + p * 1280 + 640);

            uint32_t sA0[2] = {0u, 0u}, sA1[2] = {0u, 0u};
            uint32_t sB0[2] = {0u, 0u}, sB1[2] = {0u, 0u};
            mma16h(sA0, aqA[0], k0r[0], k0r[1]);
            mma16h(sA0, aqA[1], k0r[2], k0r[3]);
            mma16h(sB0, aqB[0], k0r[0], k0r[1]);
            mma16h(sB0, aqB[1], k0r[2], k0r[3]);
            mma16h(sA1, aqA[0], k1r[0], k1r[1]);
            mma16h(sA1, aqA[1], k1r[2], k1r[3]);
            mma16h(sB1, aqB[0], k1r[0], k1r[1]);
            mma16h(sB1, aqB[1], k1r[2], k1r[3]);

            uint32_t apA[4], apB[4];
            apA[0] = ex2_h2(sA0[0]);
            apA[1] = ex2_h2(sA0[1]);
            apA[2] = ex2_h2(sA1[0]);
            apA[3] = ex2_h2(sA1[1]);
            apB[0] = ex2_h2(sB0[0]);
            apB[1] = ex2_h2(sB0[1]);
            apB[2] = ex2_h2(sB1[0]);
            apB[3] = ex2_h2(sB1[1]);

            const uint32_t* v0 = Vb + (p * 8 + tig) * 40;
            const uint32_t* v1 = Vb + (p * 8 + tig + 4) * 40;
#pragma unroll
            for (int m = 0; m < 4; m++) {
                uint32_t vb0 = v0[m * 8 + g];
                uint32_t vb1 = v1[m * 8 + g];
                mma16f(oaccA[m], apA, vb0, vb1);
                mma16f(oaccB[m], apB, vb0, vb1);
            }
            mma16f(sumA, apA, ONES, ONES);
            mma16f(sumB, apB, ONES, ONES);
        }

        stage  = stage  == 2 ? 0 : stage + 1;
        wstage = wstage == 2 ? 0 : wstage + 1;
    }

    float iA0 = 1.0f / sumA[0], iA1 = 1.0f / sumA[2];
    float iB0 = 1.0f / sumB[0], iB1 = 1.0f / sumB[2];

    int rowA = b * 2048 + qt * 256 + warp * 16 + g;
    int rowB = rowA + 128;
#pragma unroll
    for (int m = 0; m < 4; m++) {
        int wcol = h * 16 + m * 4 + tig;
        O[(size_t)rowA * 128 + wcol] =
            pack_f16(oaccA[m][1] * iA0, oaccA[m][0] * iA0);
        O[(size_t)(rowA + 8) * 128 + wcol] =
            pack_f16(oaccA[m][3] * iA1, oaccA[m][2] * iA1);
        O[(size_t)rowB * 128 + wcol] =
            pack_f16(oaccB[m][1] * iB0, oaccB[m][0] * iB0);
        O[(size_t)(rowB + 8) * 128 + wcol] =
            pack_f16(oaccB[m][3] * iB1, oaccB[m][2] * iB1);
    }
}

// ---------------- launcher ------------------------------------------------------
extern "C" void kernel_launch(void* const* d_in, const int* in_sizes, int n_in,
                              void* d_out, int out_size)
{
    (void)in_sizes; (void)n_in; (void)out_size;
    const float* x    = (const float*)d_in[0];
    const float* ln_g = (const float*)d_in[1];
    const float* ln_b = (const float*)d_in[2];
    const float* Wq   = (const float*)d_in[3];
    const float* bq   = (const float*)d_in[4];
    const float* Wk   = (const float*)d_in[5];
    const float* bk   = (const float*)d_in[6];
    const float* Wv   = (const float*)d_in[7];
    const float* bv   = (const float*)d_in[8];
    const float* Wo   = (const float*)d_in[9];
    const float* bo   = (const float*)d_in[10];
    float* out = (float*)d_out;

    uint32_t *xq, *xe, *xl, *wq, *wk, *wv, *wo;
    uint32_t *qp, *k1p, *k2p, *v1p, *v2p, *o0p, *o1p;
    cudaGetSymbolAddress((void**)&xq,  g_xq);
    cudaGetSymbolAddress((void**)&xe,  g_xe);
    cudaGetSymbolAddress((void**)&xl,  g_xl);
    cudaGetSymbolAddress((void**)&wq,  g_wq);
    cudaGetSymbolAddress((void**)&wk,  g_wk);
    cudaGetSymbolAddress((void**)&wv,  g_wv);
    cudaGetSymbolAddress((void**)&wo,  g_wo);
    cudaGetSymbolAddress((void**)&qp,  g_qp);
    cudaGetSymbolAddress((void**)&k1p, g_k1p);
    cudaGetSymbolAddress((void**)&k2p, g_k2p);
    cudaGetSymbolAddress((void**)&v1p, g_v1p);
    cudaGetSymbolAddress((void**)&v2p, g_v2p);
    cudaGetSymbolAddress((void**)&o0p, g_o0p);
    cudaGetSymbolAddress((void**)&o1p, g_o1p);

    const int GSMEM0 = 6 * 128 * 20 * 4;                   // 61440 B (3 stages A+W)
    const int GSMEM1 = 9 * 128 * 20 * 4;                   // 92160 B (3 stages A+A2+W)
    const int ASMEM  = (3 * 128 * 20 + 3 * 64 * 40) * 4;   // 61440 B
    cudaFuncSetAttribute(attn_kernel,      cudaFuncAttributeMaxDynamicSharedMemorySize, ASMEM);
    cudaFuncSetAttribute(gemm5h_kernel<0>, cudaFuncAttributeMaxDynamicSharedMemorySize, GSMEM0);
    cudaFuncSetAttribute(gemm5h_kernel<1>, cudaFuncAttributeMaxDynamicSharedMemorySize, GSMEM1);

    lnw_kernel<<<6656, 256>>>(x, ln_g, ln_b, xq, xe, xl,
                              Wq, Wk, Wv, Wo, wq, wk, wv, wo);            // launch 1

    const float QSC = 0.0625f * 1.44269504f;   // dim^-0.5 * log2(e)
    Jobs5 jobs = {{
        { xq, nullptr, wq, bq, nullptr, qp,  1.0f, QSC,  2 },
        { xe, nullptr, wk, bk, nullptr, k1p, 1.0f, 1.0f, 2 },
        { xe, nullptr, wv, bv, nullptr, v1p, 1.0f, 1.0f, 1 },
        { xl, nullptr, wk, bk, nullptr, k2p, 1.0f, 1.0f, 2 },
        { xl, nullptr, wv, bv, nullptr, v2p, 1.0f, 1.0f, 1 },
    }};
    gemm5h_kernel<0><<<dim3(128, 2, 5), 256, GSMEM0>>>(jobs);             // launch 2

    attn_kernel<<<1024, 256, ASMEM>>>(qp, k1p, v1p, k2p, v2p, o0p, o1p);  // launch 3

    // out = (o0 + o1) @ Wo^T + 2*bo
    Jobs5 ojob = {{
        { o0p, o1p, wo, bo, out, nullptr, 2.0f, 1.0f, 0 },
        { o0p, o1p, wo, bo, out, nullptr, 2.0f, 1.0f, 0 },
        { o0p, o1p, wo, bo, out, nullptr, 2.0f, 1.0f, 0 },
        { o0p, o1p, wo, bo, out, nullptr, 2.0f, 1.0f, 0 },
        { o0p, o1p, wo, bo, out, nullptr, 2.0f, 1.0f, 0 },
    }};
    gemm5h_kernel<1><<<dim3(128, 2, 1), 256, GSMEM1>>>(ojob);             // launch 4
}